// round 3
// baseline (speedup 1.0000x reference)
#include <cuda_runtime.h>
#include <math.h>

// Problem constants
#define Nn   100000   // num_nodes
#define Hd   128      // hidden_dim
#define Bb   512      // batch (events)
#define Dd   32       // neighbors per event
#define NEGS 5        // negative samples
#define NCTA 19       // 16 neighbor CTAs + h_u CTA + (s,hawkes) CTA + (rec_e) CTA

// ---------------- device scratch (no allocations allowed) ----------------
// float4-typed for guaranteed 16B alignment of vector accesses.
__device__ float4 z_buf4[(size_t)Nn * Hd / 4];   // mutable copy of z0 (51.2 MB)
#define z_buf ((float*)z_buf4)

__device__ float4 g_Wh4[Hd * Hd / 4];     // aligned copies of the weight matrices
__device__ float4 g_We2n4[Hd * Hd / 4];
__device__ float4 g_Wrece4[Hd * Hd / 4];
__device__ float4 g_Wrecn4[Hd * Hd / 4];

__device__ float s_buf[Hd];                // z_u @ W_e2n + b_e2n  (per step)
__device__ float r_buf[Hd];                // z_u @ W_rec_e + b_rec_e (per step)
__device__ unsigned bar_cnt;               // zero-init; returns to 0 each launch
__device__ unsigned bar_gen;               // monotonically grows; sampled at start

// ---------------- helpers ----------------
__device__ __forceinline__ float sigmoidf_(float x) {
    return 1.0f / (1.0f + expf(-x));
}
__device__ __forceinline__ float softplusf_(float x) {
    // stable: max(x,0) + log1p(exp(-|x|))
    return fmaxf(x, 0.0f) + log1pf(expf(-fabsf(x)));
}

// Sense/generation grid barrier across NCTA co-resident CTAs.
__device__ __forceinline__ void grid_barrier(unsigned& gen) {
    __syncthreads();
    if (threadIdx.x == 0) {
        __threadfence();                      // make my CTA's stores visible
        unsigned g = gen;
        unsigned a = atomicAdd(&bar_cnt, 1u);
        if (a == NCTA - 1) {
            atomicExch(&bar_cnt, 0u);
            __threadfence();
            atomicAdd(&bar_gen, 1u);          // release
        } else {
            while (atomicAdd(&bar_gen, 0u) == g) { /* spin at L2 */ }
        }
        gen = g + 1u;
        __threadfence();                      // acquire
    }
    __syncthreads();
}

// Partial matvec: warp q in 0..3 covers 32 k-values of
//   out[i] = sum_k sv[k] * W[k*128 + i]
// Each lane produces 4 output columns (one float4). Partials -> pb[q*128 + i].
__device__ __forceinline__ void matvec_part(const float4* __restrict__ W4,
                                            const float* __restrict__ sv,
                                            float* __restrict__ pb,
                                            int q, int lane) {
    float4 acc = make_float4(0.f, 0.f, 0.f, 0.f);
    const int kbase = q * 32;
#pragma unroll
    for (int kk = 0; kk < 32; kk++) {
        int k = kbase + kk;
        float v = sv[k];
        float4 wv = W4[k * 32 + lane];
        acc.x = fmaf(v, wv.x, acc.x);
        acc.y = fmaf(v, wv.y, acc.y);
        acc.z = fmaf(v, wv.z, acc.z);
        acc.w = fmaf(v, wv.w, acc.w);
    }
    reinterpret_cast<float4*>(pb + q * 128)[lane] = acc;
}

__device__ __forceinline__ float red4(const float* __restrict__ pb, int i) {
    return pb[i] + pb[128 + i] + pb[256 + i] + pb[384 + i];
}

// 128-dot of a global z row (L1-bypassed) against W_omega, warp-collective.
__device__ __forceinline__ float warp_dot_ldcg(const float* __restrict__ row,
                                               const float* __restrict__ Wo,
                                               int lane) {
    float a = 0.f;
#pragma unroll
    for (int c = 0; c < 4; c++) {
        int i = lane + 32 * c;
        a = fmaf(__ldcg(&row[i]), __ldg(&Wo[i]), a);
    }
#pragma unroll
    for (int o = 16; o > 0; o >>= 1) a += __shfl_down_sync(0xffffffffu, a, o);
    return a;
}

// ---------------- prep: aligned weight copies (scalar loads only) ---------
__global__ void prep_kernel(const float* __restrict__ Wh,
                            const float* __restrict__ We2n,
                            const float* __restrict__ Wrece,
                            const float* __restrict__ Wrecn) {
    int i = blockIdx.x * blockDim.x + threadIdx.x;
    if (i < Hd * Hd) {
        ((float*)g_Wh4)[i]    = __ldg(&Wh[i]);
        ((float*)g_We2n4)[i]  = __ldg(&We2n[i]);
        ((float*)g_Wrece4)[i] = __ldg(&Wrece[i]);
        ((float*)g_Wrecn4)[i] = __ldg(&Wrecn[i]);
    }
}

// ---------------- z0 -> z_buf copy (each launch, deterministic replays) ----
__global__ void copy_z_kernel(const float* __restrict__ z0) {
    size_t n = (size_t)Nn * Hd;
    for (size_t i = (size_t)blockIdx.x * blockDim.x + threadIdx.x; i < n;
         i += (size_t)gridDim.x * blockDim.x)
        z_buf[i] = __ldg(&z0[i]);
}

// ---------------- main persistent kernel ----------------
__global__ void __launch_bounds__(256) dyrep_main(
    const float* __restrict__ tb,      // time_bar [B, N]
    const float* __restrict__ tcur,    // time_cur [B]
    const float* __restrict__ tdelta,  // time_delta [B, 2]
    const int* __restrict__ uu,        // u [B]
    const int* __restrict__ nbi,       // neighbors [B, D]
    const int* __restrict__ ngi,       // neg_nodes [B, NEG]
    const float* __restrict__ Womega, const float* __restrict__ bomega,
    const float* __restrict__ bh,
    const float* __restrict__ be2n,
    const float* __restrict__ brece,
    const float* __restrict__ brecn,
    const float* __restrict__ Wtime,  const float* __restrict__ btime,
    const float* __restrict__ wt_,    const float* __restrict__ alpha_,
    const float* __restrict__ psi_,
    float* __restrict__ out)           // [B + B*NEG]
{
    __shared__ int   sidx[Dd];
    __shared__ int   su;
    __shared__ int   sneg[NEGS];
    __shared__ float sTd[1 + Dd];
    __shared__ __align__(16) float sv[2][Hd];
    __shared__ __align__(16) float pb[2][4 * Hd];
    __shared__ int   sen[2];

    const int cta  = blockIdx.x;
    const int tid  = threadIdx.x;
    const int w    = tid >> 5;
    const int lane = tid & 31;

    const float w_t   = __ldg(wt_);
    const float alpha = __ldg(alpha_);
    const float psi   = __ldg(psi_);
    const float b_om  = __ldg(bomega);

    unsigned gen = 0;
    if (tid == 0) gen = atomicAdd(&bar_gen, 0u);  // sample before first arrival

    for (int t = 0; t < Bb; t++) {
        // ---- prologue: indices and positional td --------------------------
        if (tid < Dd)                 sidx[tid] = __ldg(&nbi[t * Dd + tid]);
        if (tid == Dd)                su        = __ldg(&uu[t]);
        if (tid >= 33 && tid < 33 + NEGS) sneg[tid - 33] = __ldg(&ngi[t * NEGS + (tid - 33)]);
        const float tc = __ldg(&tcur[t]);
        if (tid < 1 + Dd)             sTd[tid] = tc - __ldg(&tb[(size_t)t * Nn + tid]);
        __syncthreads();

        // ---- phase A: pre-update reads + matvec partials ------------------
        if (cta < 16) {
            const int j0 = cta * 2, j1 = j0 + 1;
            const int n0 = sidx[j0], n1 = sidx[j1];
            if (tid < 128) sv[0][tid]       = __ldcg(&z_buf[(size_t)n0 * Hd + tid]);
            else           sv[1][tid - 128] = __ldcg(&z_buf[(size_t)n1 * Hd + (tid - 128)]);
            if (tid == 0) { // last duplicate j wins
                int en = 1;
                for (int j = j0 + 1; j < Dd; j++) if (sidx[j] == n0) en = 0;
                sen[0] = en;
            }
            if (tid == 1) {
                int en = 1;
                for (int j = j1 + 1; j < Dd; j++) if (sidx[j] == n1) en = 0;
                sen[1] = en;
            }
            __syncthreads();
            matvec_part(g_Wrecn4, sv[w >> 2], pb[w >> 2], w & 3, lane);
        } else if (cta == 16) {
            // mean(z_nb) then @ W_h
            if (tid < 128) {
                float acc = 0.f;
#pragma unroll
                for (int r = 0; r < Dd; r++)
                    acc += __ldcg(&z_buf[(size_t)sidx[r] * Hd + tid]);
                sv[0][tid] = acc * (1.0f / 32.0f);
            }
            if (tid == 0) { // any neighbor write to u overrides h_u
                int en = 1;
                for (int j = 0; j < Dd; j++) if (sidx[j] == su) en = 0;
                sen[0] = en;
            }
            __syncthreads();
            if (w < 4) matvec_part(g_Wh4, sv[0], pb[0], w, lane);
        } else if (cta == 17) {
            // s = z_u @ W_e2n + b_e2n   (+ all Hawkes outputs, pre-update)
            if (tid < 128) sv[0][tid] = __ldcg(&z_buf[(size_t)su * Hd + tid]);
            __syncthreads();
            if (w < 4) {
                matvec_part(g_We2n4, sv[0], pb[0], w, lane);
            } else {
                // tasks: 0 = emb_u, 1..5 = negatives
                for (int task = w - 4; task < 6; task += 4) {
                    if (task == 0) {
                        float dot = warp_dot_ldcg(&z_buf[(size_t)su * Hd], Womega, lane);
                        if (lane == 0) {
                            float tsd = tc - __ldg(&tdelta[2 * t]);
                            float g = dot + b_om + alpha * expf(-w_t * tsd);
                            out[t] = psi * softplusf_(g / psi);
                        }
                    } else {
                        int q = task - 1;
                        int node = sneg[q];
                        float dot = warp_dot_ldcg(&z_buf[(size_t)node * Hd], Womega, lane);
                        if (lane == 0) {
                            float tdn = tc - __ldg(&tb[(size_t)t * Nn + node]);
                            float g = dot + b_om + alpha * expf(-w_t * tdn);
                            out[Bb + t * NEGS + q] = psi * softplusf_(g / psi) * (1.0f / NEGS);
                        }
                    }
                }
            }
            __syncthreads();
            if (tid < 128) s_buf[tid] = red4(pb[0], tid) + __ldg(&be2n[tid]);
        } else { // cta == 18: r = z_u @ W_rec_e + b_rec_e
            if (tid < 128) sv[0][tid] = __ldcg(&z_buf[(size_t)su * Hd + tid]);
            __syncthreads();
            if (w < 4) matvec_part(g_Wrece4, sv[0], pb[0], w, lane);
            __syncthreads();
            if (tid < 128) r_buf[tid] = red4(pb[0], tid) + __ldg(&brece[tid]);
        }

        grid_barrier(gen);  // B1: all pre-update reads done; s_buf/r_buf visible

        // ---- phase B: combine, sigmoid, masked writes ---------------------
        if (cta < 16) {
            const int m = tid >> 7;
            const int i = tid & 127;
            const int j = cta * 2 + m;
            const int node = sidx[j];
            float h = __ldcg(&s_buf[i]) + red4(pb[m], i) + __ldg(&brecn[i])
                    + sTd[1 + j] * __ldg(&Wtime[i]) + __ldg(&btime[i]);
            h = sigmoidf_(h);
            if (sen[m]) z_buf[(size_t)node * Hd + i] = h;
        } else if (cta == 16) {
            if (tid < 128) {
                float h = red4(pb[0], tid) + __ldg(&bh[tid]) + __ldcg(&r_buf[tid])
                        + sTd[0] * __ldg(&Wtime[tid]) + __ldg(&btime[tid]);
                h = sigmoidf_(h);
                if (sen[0]) z_buf[(size_t)su * Hd + tid] = h;
            }
        }
        // CTAs 17/18 idle in phase B

        grid_barrier(gen);  // B2: writes visible before next step's reads
    }
}

// ---------------- launch ----------------
extern "C" void kernel_launch(void* const* d_in, const int* in_sizes, int n_in,
                              void* d_out, int out_size) {
    (void)in_sizes; (void)n_in; (void)out_size;
    const float* time_bar   = (const float*)d_in[0];
    const float* time_cur   = (const float*)d_in[1];
    const float* time_delta = (const float*)d_in[2];
    const int*   u          = (const int*)d_in[3];
    const int*   neighbors  = (const int*)d_in[4];
    const int*   neg_nodes  = (const int*)d_in[5];
    const float* z0         = (const float*)d_in[6];
    const float* W_omega    = (const float*)d_in[7];
    const float* b_omega    = (const float*)d_in[8];
    const float* W_h        = (const float*)d_in[9];
    const float* b_h        = (const float*)d_in[10];
    const float* W_e2n      = (const float*)d_in[11];
    const float* b_e2n      = (const float*)d_in[12];
    const float* W_rec_e    = (const float*)d_in[13];
    const float* b_rec_e    = (const float*)d_in[14];
    const float* W_rec_n    = (const float*)d_in[15];
    const float* b_rec_n    = (const float*)d_in[16];
    const float* W_time     = (const float*)d_in[17];
    const float* b_time     = (const float*)d_in[18];
    const float* w_t        = (const float*)d_in[19];
    const float* alpha      = (const float*)d_in[20];
    const float* psi        = (const float*)d_in[21];

    prep_kernel<<<64, 256>>>(W_h, W_e2n, W_rec_e, W_rec_n);
    copy_z_kernel<<<2048, 256>>>(z0);
    dyrep_main<<<NCTA, 256>>>(time_bar, time_cur, time_delta, u, neighbors,
                              neg_nodes, W_omega, b_omega, b_h,
                              b_e2n, b_rec_e, b_rec_n,
                              W_time, b_time, w_t, alpha, psi, (float*)d_out);
}